// round 10
// baseline (speedup 1.0000x reference)
#include <cuda_runtime.h>
#include <cuda_bf16.h>
#include <math.h>
#include <stdint.h>

// Problem constants
#define B_SZ   128
#define T_SEQ  256
#define EMB    384
#define NH     6
#define HD     64
#define WIN    64
#define M_ROWS (B_SZ * T_SEQ)        // 32768
#define QKV_N  (3 * EMB)             // 1152

// Scratch (no cudaMalloc allowed) — device globals.
__device__ float g_qkv[(size_t)M_ROWS * QKV_N];  // [M, 1152]
__device__ float g_y[(size_t)M_ROWS * EMB];      // [M, 384]

// ---------------------------------------------------------------------------
// tf32 helpers
// ---------------------------------------------------------------------------
__device__ __forceinline__ float to_tf32(float x) {
    uint32_t u;
    asm("cvt.rna.tf32.f32 %0, %1;" : "=r"(u) : "f"(x));
    return __uint_as_float(u);
}
__device__ __forceinline__ uint32_t tf32u(float x) {
    uint32_t u;
    asm("cvt.rna.tf32.f32 %0, %1;" : "=r"(u) : "f"(x));
    return u;
}

__device__ __forceinline__ void mma_tf32(float c[4],
    uint32_t a0, uint32_t a1, uint32_t a2, uint32_t a3,
    uint32_t b0, uint32_t b1)
{
    asm volatile(
        "mma.sync.aligned.m16n8k8.row.col.f32.tf32.tf32.f32 "
        "{%0,%1,%2,%3}, {%4,%5,%6,%7}, {%8,%9}, {%0,%1,%2,%3};"
        : "+f"(c[0]), "+f"(c[1]), "+f"(c[2]), "+f"(c[3])
        : "r"(a0), "r"(a1), "r"(a2), "r"(a3), "r"(b0), "r"(b1));
}

__device__ __forceinline__ void cp_async16(uint32_t saddr, const float* g) {
    asm volatile("cp.async.cg.shared.global [%0], [%1], 16;" :: "r"(saddr), "l"(g));
}
#define CP_COMMIT() asm volatile("cp.async.commit_group;" ::: "memory")
#define CP_WAIT(n)  asm volatile("cp.async.wait_group %0;" :: "n"(n) : "memory")

// ---------------------------------------------------------------------------
// tf32 tensor-core GEMM with 3-stage cp.async pipeline.
// C[M,N] = A[M,384] @ B[384,N] + bias[N]
// BM=128, BN=128, BK=16, 256 threads (8 warps 2x4), warp tile 64x32.
// A smem [m][k] stride 20; B smem [k][n] stride 136 (both frag-conflict-free).
// tf32 conversion at fragment load (fma pipe idle). One sync per k-tile.
// ---------------------------------------------------------------------------
#define GBM 128
#define GBN 128
#define GBK 16
#define AS_ST 20
#define BS_ST 136
#define NKT (EMB / GBK)       // 24
#define STAGES 3
#define AS_STAGE (GBM * AS_ST)   // 2560 floats
#define BS_STAGE (GBK * BS_ST)   // 2176 floats
#define GEMM_SMEM_F (STAGES * (AS_STAGE + BS_STAGE))   // 14208 floats = 56832 B

__global__ __launch_bounds__(256) void gemm_tf32_kernel(
    const float* __restrict__ A, const float* __restrict__ Bm,
    const float* __restrict__ bias, float* __restrict__ C, int N)
{
    extern __shared__ float smem[];
    float* As = smem;                          // [STAGES][GBM][AS_ST]
    float* Bs = smem + STAGES * AS_STAGE;      // [STAGES][GBK][BS_ST]
    const uint32_t smem_base = (uint32_t)__cvta_generic_to_shared(smem);
    const uint32_t bs_base   = smem_base + STAGES * AS_STAGE * 4u;

    const int tid  = threadIdx.x;
    const int lane = tid & 31;
    const int wid  = tid >> 5;
    const int warp_m = wid >> 2;   // 0..1
    const int warp_n = wid & 3;    // 0..3
    const int m0 = blockIdx.y * GBM;
    const int n0 = blockIdx.x * GBN;

    // loaders
    const int ar = tid >> 2;          // 0..63 (rows ar, ar+64)
    const int ak = (tid & 3) * 4;     // 0,4,8,12
    const int bk = tid >> 4;          // 0..15
    const int bn = (tid & 15) * 4;    // 0..60 (cols bn, bn+64)

    const float* Ag = A + (size_t)m0 * EMB;
    const float* Bg = Bm + n0;

    // per-thread smem dst byte offsets within a stage
    const uint32_t a_off0 = (uint32_t)((ar * AS_ST + ak) * 4);
    const uint32_t a_off1 = (uint32_t)(((ar + 64) * AS_ST + ak) * 4);
    const uint32_t b_off0 = (uint32_t)((bk * BS_ST + bn) * 4);
    const uint32_t b_off1 = (uint32_t)((bk * BS_ST + bn + 64) * 4);

    auto issue_stage = [&](int kt, int s) {
        const int k0 = kt * GBK;
        const uint32_t as_s = smem_base + (uint32_t)(s * AS_STAGE * 4);
        const uint32_t bs_s = bs_base   + (uint32_t)(s * BS_STAGE * 4);
        cp_async16(as_s + a_off0, Ag + (size_t)ar * EMB + k0 + ak);
        cp_async16(as_s + a_off1, Ag + (size_t)(ar + 64) * EMB + k0 + ak);
        cp_async16(bs_s + b_off0, Bg + (size_t)(k0 + bk) * N + bn);
        cp_async16(bs_s + b_off1, Bg + (size_t)(k0 + bk) * N + bn + 64);
        CP_COMMIT();
    };

    float c[4][4][4];
    #pragma unroll
    for (int mt = 0; mt < 4; mt++)
        #pragma unroll
        for (int nt = 0; nt < 4; nt++)
            #pragma unroll
            for (int i = 0; i < 4; i++) c[mt][nt][i] = 0.f;

    // prologue: fill STAGES-1 stages
    #pragma unroll
    for (int s = 0; s < STAGES - 1; s++) issue_stage(s, s);

    const int lg = lane >> 2;
    const int lt = lane & 3;

    #pragma unroll 1
    for (int kt = 0; kt < NKT; kt++) {
        if (kt == NKT - 1) { CP_WAIT(0); } else { CP_WAIT(STAGES - 2); }
        __syncthreads();

        // issue the next stage (reuses the stage read in iteration kt-1;
        // all threads passed that read via the sync above)
        const int nk = kt + STAGES - 1;
        if (nk < NKT) issue_stage(nk, nk % STAGES);

        const int s = kt % STAGES;
        const float* as = As + s * AS_STAGE;
        const float* bs = Bs + s * BS_STAGE;

        #pragma unroll
        for (int ks = 0; ks < GBK; ks += 8) {
            uint32_t bf[4][2];
            #pragma unroll
            for (int nt = 0; nt < 4; nt++) {
                const int nb = warp_n * 32 + nt * 8 + lg;
                bf[nt][0] = tf32u(bs[(ks + lt) * BS_ST + nb]);
                bf[nt][1] = tf32u(bs[(ks + 4 + lt) * BS_ST + nb]);
            }
            #pragma unroll
            for (int mt = 0; mt < 4; mt++) {
                const int mb = warp_m * 64 + mt * 16 + lg;
                uint32_t a0 = tf32u(as[mb * AS_ST + ks + lt]);
                uint32_t a1 = tf32u(as[(mb + 8) * AS_ST + ks + lt]);
                uint32_t a2 = tf32u(as[mb * AS_ST + ks + 4 + lt]);
                uint32_t a3 = tf32u(as[(mb + 8) * AS_ST + ks + 4 + lt]);
                #pragma unroll
                for (int nt = 0; nt < 4; nt++)
                    mma_tf32(c[mt][nt], a0, a1, a2, a3, bf[nt][0], bf[nt][1]);
            }
        }
        __syncthreads();
    }

    // epilogue: add bias, store
    #pragma unroll
    for (int mt = 0; mt < 4; mt++) {
        const int row = m0 + warp_m * 64 + mt * 16 + lg;
        #pragma unroll
        for (int nt = 0; nt < 4; nt++) {
            const int col = n0 + warp_n * 32 + nt * 8 + lt * 2;
            const float b0 = bias[col], b1 = bias[col + 1];
            float2 v0 = make_float2(c[mt][nt][0] + b0, c[mt][nt][1] + b1);
            float2 v1 = make_float2(c[mt][nt][2] + b0, c[mt][nt][3] + b1);
            *(float2*)&C[(size_t)row * N + col]       = v0;
            *(float2*)&C[(size_t)(row + 8) * N + col] = v1;
        }
    }
}

// ---------------------------------------------------------------------------
// Banded causal attention — tensor-core version (unchanged from round 7).
// ---------------------------------------------------------------------------
#define QT 64
#define KT 128
#define QS_ST 68
#define KS_ST 68
#define VT_ST 132
#define SS_ST 136

#define SM_VT   0
#define SM_Q    (64 * VT_ST)
#define SM_K    (SM_Q + QT * QS_ST)
#define SM_S    SM_Q
#define SM_TOTF (SM_K + KT * KS_ST)   // 21504 floats = 84 KB

__global__ __launch_bounds__(256, 2) void attn_kernel(
    const float* __restrict__ qkv, float* __restrict__ y)
{
    extern __shared__ float sm[];
    float* Vt = sm + SM_VT;
    float* Qs = sm + SM_Q;
    float* Ks = sm + SM_K;
    float* Ss = sm + SM_S;

    const int q0  = blockIdx.x * QT;
    const int h   = blockIdx.y;
    const int b   = blockIdx.z;
    const int tid = threadIdx.x;
    const int hoff = h * HD;

    const float* base = qkv + (size_t)b * T_SEQ * QKV_N;

    for (int idx = tid; idx < KT * 16; idx += 256) {
        const int s = idx >> 4, f = idx & 15;
        const int j = q0 - WIN + s;
        float4 kv, vv;
        if (j >= 0 && j < T_SEQ) {
            const float* row = base + (size_t)j * QKV_N;
            kv = *(const float4*)(row + EMB     + hoff + f * 4);
            vv = *(const float4*)(row + 2 * EMB + hoff + f * 4);
        } else {
            kv = make_float4(0.f, 0.f, 0.f, 0.f);
            vv = kv;
        }
        float4 t;
        t.x = to_tf32(kv.x); t.y = to_tf32(kv.y); t.z = to_tf32(kv.z); t.w = to_tf32(kv.w);
        *(float4*)(Ks + s * KS_ST + f * 4) = t;
        Vt[(f * 4 + 0) * VT_ST + s] = to_tf32(vv.x);
        Vt[(f * 4 + 1) * VT_ST + s] = to_tf32(vv.y);
        Vt[(f * 4 + 2) * VT_ST + s] = to_tf32(vv.z);
        Vt[(f * 4 + 3) * VT_ST + s] = to_tf32(vv.w);
    }
    for (int idx = tid; idx < QT * 16; idx += 256) {
        const int qi = idx >> 4, f = idx & 15;
        const float* row = base + (size_t)(q0 + qi) * QKV_N;
        float4 q4 = *(const float4*)(row + hoff + f * 4);
        float4 t;
        t.x = to_tf32(q4.x); t.y = to_tf32(q4.y); t.z = to_tf32(q4.z); t.w = to_tf32(q4.w);
        *(float4*)(Qs + qi * QS_ST + f * 4) = t;
    }
    __syncthreads();

    const int lane = tid & 31;
    const int wid  = tid >> 5;
    const int lg = lane >> 2;
    const int lt = lane & 3;
    const int mt = wid & 3;
    const int nh = wid >> 2;

    float sc[8][4];
    #pragma unroll
    for (int nt = 0; nt < 8; nt++)
        #pragma unroll
        for (int i = 0; i < 4; i++) sc[nt][i] = 0.f;

    const int mrow = mt * 16 + lg;
    #pragma unroll
    for (int k0 = 0; k0 < HD; k0 += 8) {
        uint32_t a0 = __float_as_uint(Qs[mrow * QS_ST + k0 + lt]);
        uint32_t a1 = __float_as_uint(Qs[(mrow + 8) * QS_ST + k0 + lt]);
        uint32_t a2 = __float_as_uint(Qs[mrow * QS_ST + k0 + 4 + lt]);
        uint32_t a3 = __float_as_uint(Qs[(mrow + 8) * QS_ST + k0 + 4 + lt]);
        #pragma unroll
        for (int nt = 0; nt < 8; nt++) {
            const int nb = nh * 64 + nt * 8 + lg;
            uint32_t b0 = __float_as_uint(Ks[nb * KS_ST + k0 + lt]);
            uint32_t b1 = __float_as_uint(Ks[nb * KS_ST + k0 + 4 + lt]);
            mma_tf32(sc[nt], a0, a1, a2, a3, b0, b1);
        }
    }
    __syncthreads();

    #pragma unroll
    for (int nt = 0; nt < 8; nt++) {
        const int col = nh * 64 + nt * 8 + lt * 2;
        *(float2*)(Ss + mrow * SS_ST + col)       = make_float2(sc[nt][0], sc[nt][1]);
        *(float2*)(Ss + (mrow + 8) * SS_ST + col) = make_float2(sc[nt][2], sc[nt][3]);
    }
    __syncthreads();

    {
        const int qi = tid >> 2;
        const int kg = tid & 3;
        const int smin = max(qi, WIN - q0);
        const int smax = qi + WIN;
        float* srow = Ss + qi * SS_ST;

        float v[32];
        float m = -1e30f;
        #pragma unroll
        for (int si = 0; si < 32; si++) {
            const int s = si * 4 + kg;
            const bool ok = (s >= smin) && (s <= smax);
            float t = ok ? srow[s] * 0.125f : -1e30f;
            v[si] = t;
            m = fmaxf(m, t);
        }
        m = fmaxf(m, __shfl_xor_sync(0xffffffffu, m, 1));
        m = fmaxf(m, __shfl_xor_sync(0xffffffffu, m, 2));
        float ssum = 0.f;
        #pragma unroll
        for (int si = 0; si < 32; si++) {
            float e = __expf(v[si] - m);
            v[si] = e;
            ssum += e;
        }
        ssum += __shfl_xor_sync(0xffffffffu, ssum, 1);
        ssum += __shfl_xor_sync(0xffffffffu, ssum, 2);
        const float inv = 1.f / ssum;
        #pragma unroll
        for (int si = 0; si < 32; si++)
            srow[si * 4 + kg] = to_tf32(v[si] * inv);
    }
    __syncthreads();

    float oc[4][4];
    #pragma unroll
    for (int nt = 0; nt < 4; nt++)
        #pragma unroll
        for (int i = 0; i < 4; i++) oc[nt][i] = 0.f;

    #pragma unroll
    for (int k0 = 0; k0 < KT; k0 += 8) {
        uint32_t a0 = __float_as_uint(Ss[mrow * SS_ST + k0 + lt]);
        uint32_t a1 = __float_as_uint(Ss[(mrow + 8) * SS_ST + k0 + lt]);
        uint32_t a2 = __float_as_uint(Ss[mrow * SS_ST + k0 + 4 + lt]);
        uint32_t a3 = __float_as_uint(Ss[(mrow + 8) * SS_ST + k0 + 4 + lt]);
        #pragma unroll
        for (int nt = 0; nt < 4; nt++) {
            const int nb = nh * 32 + nt * 8 + lg;
            uint32_t b0 = __float_as_uint(Vt[nb * VT_ST + k0 + lt]);
            uint32_t b1 = __float_as_uint(Vt[nb * VT_ST + k0 + 4 + lt]);
            mma_tf32(oc[nt], a0, a1, a2, a3, b0, b1);
        }
    }

    {
        const int row0 = b * T_SEQ + q0 + mrow;
        #pragma unroll
        for (int nt = 0; nt < 4; nt++) {
            const int col = hoff + nh * 32 + nt * 8 + lt * 2;
            *(float2*)(y + (size_t)row0 * EMB + col)
                = make_float2(oc[nt][0], oc[nt][1]);
            *(float2*)(y + (size_t)(row0 + 8) * EMB + col)
                = make_float2(oc[nt][2], oc[nt][3]);
        }
    }
}

// ---------------------------------------------------------------------------
// Launch
// ---------------------------------------------------------------------------
extern "C" void kernel_launch(void* const* d_in, const int* in_sizes, int n_in,
                              void* d_out, int out_size)
{
    const float* x      = (const float*)d_in[0];  // [128,256,384]
    const float* W_attn = (const float*)d_in[1];  // [384,1152]
    const float* b_attn = (const float*)d_in[2];  // [1152]
    const float* W_proj = (const float*)d_in[3];  // [384,384]
    const float* b_proj = (const float*)d_in[4];  // [384]
    float* out = (float*)d_out;                   // [128,256,384]

    float *qkv_ptr = nullptr, *y_ptr = nullptr;
    cudaGetSymbolAddress((void**)&qkv_ptr, g_qkv);
    cudaGetSymbolAddress((void**)&y_ptr, g_y);

    const int gemm_smem = GEMM_SMEM_F * (int)sizeof(float);   // 56832 B
    cudaFuncSetAttribute(gemm_tf32_kernel, cudaFuncAttributeMaxDynamicSharedMemorySize, gemm_smem);

    // 1) qkv = x @ W_attn + b_attn   (tf32 tensor cores, cp.async pipeline)
    {
        dim3 grid(QKV_N / GBN, M_ROWS / GBM);
        gemm_tf32_kernel<<<grid, 256, gemm_smem>>>(x, W_attn, b_attn, qkv_ptr, QKV_N);
    }

    // 2) banded attention (tensor cores) -> g_y
    {
        const int smem_bytes = SM_TOTF * (int)sizeof(float);   // 84 KB
        cudaFuncSetAttribute(attn_kernel, cudaFuncAttributeMaxDynamicSharedMemorySize, smem_bytes);
        dim3 grid(T_SEQ / QT, NH, B_SZ);
        attn_kernel<<<grid, 256, smem_bytes>>>(qkv_ptr, y_ptr);
    }

    // 3) out = y @ W_proj + b_proj   (tf32 tensor cores, cp.async pipeline)
    {
        dim3 grid(EMB / GBN, M_ROWS / GBM);
        gemm_tf32_kernel<<<grid, 256, gemm_smem>>>(y_ptr, W_proj, b_proj, out, EMB);
    }
}

// round 13
// speedup vs baseline: 1.5928x; 1.5928x over previous
#include <cuda_runtime.h>
#include <cuda_bf16.h>
#include <math.h>
#include <stdint.h>

// Problem constants
#define B_SZ   128
#define T_SEQ  256
#define EMB    384
#define NH     6
#define HD     64
#define WIN    64
#define M_ROWS (B_SZ * T_SEQ)        // 32768
#define QKV_N  (3 * EMB)             // 1152

// Scratch (no cudaMalloc allowed) — device globals.
__device__ float g_qkv[(size_t)M_ROWS * QKV_N];  // [M, 1152]
__device__ float g_y[(size_t)M_ROWS * EMB];      // [M, 384] (tf32-rounded by attn)
__device__ float g_xr[(size_t)M_ROWS * EMB];     // tf32-rounded x
__device__ float g_war[(size_t)EMB * QKV_N];     // tf32-rounded W_attn
__device__ float g_wpr[(size_t)EMB * EMB];       // tf32-rounded W_proj

// ---------------------------------------------------------------------------
// tf32 helpers
// ---------------------------------------------------------------------------
__device__ __forceinline__ float to_tf32(float x) {
    uint32_t u;
    asm("cvt.rna.tf32.f32 %0, %1;" : "=r"(u) : "f"(x));
    return __uint_as_float(u);
}

__device__ __forceinline__ void mma_tf32(float c[4],
    uint32_t a0, uint32_t a1, uint32_t a2, uint32_t a3,
    uint32_t b0, uint32_t b1)
{
    asm volatile(
        "mma.sync.aligned.m16n8k8.row.col.f32.tf32.tf32.f32 "
        "{%0,%1,%2,%3}, {%4,%5,%6,%7}, {%8,%9}, {%0,%1,%2,%3};"
        : "+f"(c[0]), "+f"(c[1]), "+f"(c[2]), "+f"(c[3])
        : "r"(a0), "r"(a1), "r"(a2), "r"(a3), "r"(b0), "r"(b1));
}

__device__ __forceinline__ void cp_async16(uint32_t saddr, const float* g) {
    asm volatile("cp.async.cg.shared.global [%0], [%1], 16;" :: "r"(saddr), "l"(g));
}
#define CP_COMMIT() asm volatile("cp.async.commit_group;" ::: "memory")
#define CP_WAIT(n)  asm volatile("cp.async.wait_group %0;" :: "n"(n) : "memory")

// ---------------------------------------------------------------------------
// Pre-round kernel: out[i] = tf32(in[i]) (vectorized, grid-stride)
// ---------------------------------------------------------------------------
__global__ void round_tf32_kernel(const float* __restrict__ in,
                                  float* __restrict__ out, int n4)
{
    for (int i = blockIdx.x * blockDim.x + threadIdx.x; i < n4;
         i += gridDim.x * blockDim.x) {
        float4 v = ((const float4*)in)[i];
        v.x = to_tf32(v.x); v.y = to_tf32(v.y);
        v.z = to_tf32(v.z); v.w = to_tf32(v.w);
        ((float4*)out)[i] = v;
    }
}

// ---------------------------------------------------------------------------
// tf32 tensor-core GEMM, 4-stage cp.async pipeline, NO conversion anywhere
// (inputs pre-rounded). C[M,N] = A[M,384] @ B[384,N] + bias[N]
// BM=128, BN=128, BK=16, 256 threads (8 warps 2x4), warp tile 64x32.
// A smem [m][k] stride 20; B smem [k][n] stride 136 (frag-conflict-free).
// One __syncthreads per k-tile.
// ---------------------------------------------------------------------------
#define GBM 128
#define GBN 128
#define GBK 16
#define AS_ST 20
#define BS_ST 136
#define NKT (EMB / GBK)          // 24
#define STAGES 4
#define AS_STAGE (GBM * AS_ST)   // 2560 floats
#define BS_STAGE (GBK * BS_ST)   // 2176 floats
#define GEMM_SMEM_F (STAGES * (AS_STAGE + BS_STAGE))   // 18944 floats = 75776 B

__global__ __launch_bounds__(256) void gemm_tf32_kernel(
    const float* __restrict__ A, const float* __restrict__ Bm,
    const float* __restrict__ bias, float* __restrict__ C, int N)
{
    extern __shared__ float smem[];
    float* As = smem;                          // [STAGES][GBM][AS_ST]
    float* Bs = smem + STAGES * AS_STAGE;      // [STAGES][GBK][BS_ST]
    const uint32_t smem_base = (uint32_t)__cvta_generic_to_shared(smem);
    const uint32_t bs_base   = smem_base + STAGES * AS_STAGE * 4u;

    const int tid  = threadIdx.x;
    const int lane = tid & 31;
    const int wid  = tid >> 5;
    const int warp_m = wid >> 2;   // 0..1
    const int warp_n = wid & 3;    // 0..3
    const int m0 = blockIdx.y * GBM;
    const int n0 = blockIdx.x * GBN;

    const int ar = tid >> 2;          // 0..63 (rows ar, ar+64)
    const int ak = (tid & 3) * 4;     // 0,4,8,12
    const int bk = tid >> 4;          // 0..15
    const int bn = (tid & 15) * 4;    // 0..60 (cols bn, bn+64)

    const float* Ag = A + (size_t)m0 * EMB;
    const float* Bg = Bm + n0;

    const uint32_t a_off0 = (uint32_t)((ar * AS_ST + ak) * 4);
    const uint32_t a_off1 = (uint32_t)(((ar + 64) * AS_ST + ak) * 4);
    const uint32_t b_off0 = (uint32_t)((bk * BS_ST + bn) * 4);
    const uint32_t b_off1 = (uint32_t)((bk * BS_ST + bn + 64) * 4);

    auto issue_stage = [&](int kt, int s) {
        const int k0 = kt * GBK;
        const uint32_t as_s = smem_base + (uint32_t)(s * AS_STAGE * 4);
        const uint32_t bs_s = bs_base   + (uint32_t)(s * BS_STAGE * 4);
        cp_async16(as_s + a_off0, Ag + (size_t)ar * EMB + k0 + ak);
        cp_async16(as_s + a_off1, Ag + (size_t)(ar + 64) * EMB + k0 + ak);
        cp_async16(bs_s + b_off0, Bg + (size_t)(k0 + bk) * N + bn);
        cp_async16(bs_s + b_off1, Bg + (size_t)(k0 + bk) * N + bn + 64);
        CP_COMMIT();
    };

    float c[4][4][4];
    #pragma unroll
    for (int mt = 0; mt < 4; mt++)
        #pragma unroll
        for (int nt = 0; nt < 4; nt++)
            #pragma unroll
            for (int i = 0; i < 4; i++) c[mt][nt][i] = 0.f;

    // prologue: fill STAGES-1 stages
    #pragma unroll
    for (int s = 0; s < STAGES - 1; s++) issue_stage(s, s);

    const int lg = lane >> 2;
    const int lt = lane & 3;

    #pragma unroll 1
    for (int kt = 0; kt < NKT; kt++) {
        CP_WAIT(STAGES - 2);
        // This barrier also proves every warp finished reading stage
        // (kt-1)%STAGES (consumed last iteration), which is exactly the
        // stage issue_stage below overwrites: (kt+STAGES-1)%STAGES.
        __syncthreads();

        const int nk = kt + STAGES - 1;
        if (nk < NKT) issue_stage(nk, nk % STAGES);

        const int s = kt % STAGES;
        const float* as = As + s * AS_STAGE;
        const float* bs = Bs + s * BS_STAGE;

        #pragma unroll
        for (int ks = 0; ks < GBK; ks += 8) {
            uint32_t bf[4][2];
            #pragma unroll
            for (int nt = 0; nt < 4; nt++) {
                const int nb = warp_n * 32 + nt * 8 + lg;
                bf[nt][0] = __float_as_uint(bs[(ks + lt) * BS_ST + nb]);
                bf[nt][1] = __float_as_uint(bs[(ks + 4 + lt) * BS_ST + nb]);
            }
            #pragma unroll
            for (int mt = 0; mt < 4; mt++) {
                const int mb = warp_m * 64 + mt * 16 + lg;
                uint32_t a0 = __float_as_uint(as[mb * AS_ST + ks + lt]);
                uint32_t a1 = __float_as_uint(as[(mb + 8) * AS_ST + ks + lt]);
                uint32_t a2 = __float_as_uint(as[mb * AS_ST + ks + 4 + lt]);
                uint32_t a3 = __float_as_uint(as[(mb + 8) * AS_ST + ks + 4 + lt]);
                #pragma unroll
                for (int nt = 0; nt < 4; nt++)
                    mma_tf32(c[mt][nt], a0, a1, a2, a3, bf[nt][0], bf[nt][1]);
            }
        }
    }

    // epilogue: add bias, store
    #pragma unroll
    for (int mt = 0; mt < 4; mt++) {
        const int row = m0 + warp_m * 64 + mt * 16 + lg;
        #pragma unroll
        for (int nt = 0; nt < 4; nt++) {
            const int col = n0 + warp_n * 32 + nt * 8 + lt * 2;
            const float b0 = bias[col], b1 = bias[col + 1];
            float2 v0 = make_float2(c[mt][nt][0] + b0, c[mt][nt][1] + b1);
            float2 v1 = make_float2(c[mt][nt][2] + b0, c[mt][nt][3] + b1);
            *(float2*)&C[(size_t)row * N + col]       = v0;
            *(float2*)&C[(size_t)(row + 8) * N + col] = v1;
        }
    }
}

// ---------------------------------------------------------------------------
// Banded causal attention — tensor-core version.
// Identical to the passing round-7 kernel except the epilogue writes
// tf32-rounded y (so GEMM2 needs no conversion).
// ---------------------------------------------------------------------------
#define QT 64
#define KT 128
#define QS_ST 68
#define KS_ST 68
#define VT_ST 132
#define SS_ST 136

#define SM_VT   0
#define SM_Q    (64 * VT_ST)
#define SM_K    (SM_Q + QT * QS_ST)
#define SM_S    SM_Q
#define SM_TOTF (SM_K + KT * KS_ST)   // 21504 floats = 84 KB

__global__ __launch_bounds__(256, 2) void attn_kernel(
    const float* __restrict__ qkv, float* __restrict__ y)
{
    extern __shared__ float sm[];
    float* Vt = sm + SM_VT;
    float* Qs = sm + SM_Q;
    float* Ks = sm + SM_K;
    float* Ss = sm + SM_S;

    const int q0  = blockIdx.x * QT;
    const int h   = blockIdx.y;
    const int b   = blockIdx.z;
    const int tid = threadIdx.x;
    const int hoff = h * HD;

    const float* base = qkv + (size_t)b * T_SEQ * QKV_N;

    for (int idx = tid; idx < KT * 16; idx += 256) {
        const int s = idx >> 4, f = idx & 15;
        const int j = q0 - WIN + s;
        float4 kv, vv;
        if (j >= 0 && j < T_SEQ) {
            const float* row = base + (size_t)j * QKV_N;
            kv = *(const float4*)(row + EMB     + hoff + f * 4);
            vv = *(const float4*)(row + 2 * EMB + hoff + f * 4);
        } else {
            kv = make_float4(0.f, 0.f, 0.f, 0.f);
            vv = kv;
        }
        float4 t;
        t.x = to_tf32(kv.x); t.y = to_tf32(kv.y); t.z = to_tf32(kv.z); t.w = to_tf32(kv.w);
        *(float4*)(Ks + s * KS_ST + f * 4) = t;
        Vt[(f * 4 + 0) * VT_ST + s] = to_tf32(vv.x);
        Vt[(f * 4 + 1) * VT_ST + s] = to_tf32(vv.y);
        Vt[(f * 4 + 2) * VT_ST + s] = to_tf32(vv.z);
        Vt[(f * 4 + 3) * VT_ST + s] = to_tf32(vv.w);
    }
    for (int idx = tid; idx < QT * 16; idx += 256) {
        const int qi = idx >> 4, f = idx & 15;
        const float* row = base + (size_t)(q0 + qi) * QKV_N;
        float4 q4 = *(const float4*)(row + hoff + f * 4);
        float4 t;
        t.x = to_tf32(q4.x); t.y = to_tf32(q4.y); t.z = to_tf32(q4.z); t.w = to_tf32(q4.w);
        *(float4*)(Qs + qi * QS_ST + f * 4) = t;
    }
    __syncthreads();

    const int lane = tid & 31;
    const int wid  = tid >> 5;
    const int lg = lane >> 2;
    const int lt = lane & 3;
    const int mt = wid & 3;
    const int nh = wid >> 2;

    float sc[8][4];
    #pragma unroll
    for (int nt = 0; nt < 8; nt++)
        #pragma unroll
        for (int i = 0; i < 4; i++) sc[nt][i] = 0.f;

    const int mrow = mt * 16 + lg;
    #pragma unroll
    for (int k0 = 0; k0 < HD; k0 += 8) {
        uint32_t a0 = __float_as_uint(Qs[mrow * QS_ST + k0 + lt]);
        uint32_t a1 = __float_as_uint(Qs[(mrow + 8) * QS_ST + k0 + lt]);
        uint32_t a2 = __float_as_uint(Qs[mrow * QS_ST + k0 + 4 + lt]);
        uint32_t a3 = __float_as_uint(Qs[(mrow + 8) * QS_ST + k0 + 4 + lt]);
        #pragma unroll
        for (int nt = 0; nt < 8; nt++) {
            const int nb = nh * 64 + nt * 8 + lg;
            uint32_t b0 = __float_as_uint(Ks[nb * KS_ST + k0 + lt]);
            uint32_t b1 = __float_as_uint(Ks[nb * KS_ST + k0 + 4 + lt]);
            mma_tf32(sc[nt], a0, a1, a2, a3, b0, b1);
        }
    }
    __syncthreads();

    #pragma unroll
    for (int nt = 0; nt < 8; nt++) {
        const int col = nh * 64 + nt * 8 + lt * 2;
        *(float2*)(Ss + mrow * SS_ST + col)       = make_float2(sc[nt][0], sc[nt][1]);
        *(float2*)(Ss + (mrow + 8) * SS_ST + col) = make_float2(sc[nt][2], sc[nt][3]);
    }
    __syncthreads();

    {
        const int qi = tid >> 2;
        const int kg = tid & 3;
        const int smin = max(qi, WIN - q0);
        const int smax = qi + WIN;
        float* srow = Ss + qi * SS_ST;

        float v[32];
        float m = -1e30f;
        #pragma unroll
        for (int si = 0; si < 32; si++) {
            const int s = si * 4 + kg;
            const bool ok = (s >= smin) && (s <= smax);
            float t = ok ? srow[s] * 0.125f : -1e30f;
            v[si] = t;
            m = fmaxf(m, t);
        }
        m = fmaxf(m, __shfl_xor_sync(0xffffffffu, m, 1));
        m = fmaxf(m, __shfl_xor_sync(0xffffffffu, m, 2));
        float ssum = 0.f;
        #pragma unroll
        for (int si = 0; si < 32; si++) {
            float e = __expf(v[si] - m);
            v[si] = e;
            ssum += e;
        }
        ssum += __shfl_xor_sync(0xffffffffu, ssum, 1);
        ssum += __shfl_xor_sync(0xffffffffu, ssum, 2);
        const float inv = 1.f / ssum;
        #pragma unroll
        for (int si = 0; si < 32; si++)
            srow[si * 4 + kg] = to_tf32(v[si] * inv);
    }
    __syncthreads();

    float oc[4][4];
    #pragma unroll
    for (int nt = 0; nt < 4; nt++)
        #pragma unroll
        for (int i = 0; i < 4; i++) oc[nt][i] = 0.f;

    #pragma unroll
    for (int k0 = 0; k0 < KT; k0 += 8) {
        uint32_t a0 = __float_as_uint(Ss[mrow * SS_ST + k0 + lt]);
        uint32_t a1 = __float_as_uint(Ss[(mrow + 8) * SS_ST + k0 + lt]);
        uint32_t a2 = __float_as_uint(Ss[mrow * SS_ST + k0 + 4 + lt]);
        uint32_t a3 = __float_as_uint(Ss[(mrow + 8) * SS_ST + k0 + 4 + lt]);
        #pragma unroll
        for (int nt = 0; nt < 4; nt++) {
            const int nb = nh * 32 + nt * 8 + lg;
            uint32_t b0 = __float_as_uint(Vt[nb * VT_ST + k0 + lt]);
            uint32_t b1 = __float_as_uint(Vt[nb * VT_ST + k0 + 4 + lt]);
            mma_tf32(oc[nt], a0, a1, a2, a3, b0, b1);
        }
    }

    {
        const int row0 = b * T_SEQ + q0 + mrow;
        #pragma unroll
        for (int nt = 0; nt < 4; nt++) {
            const int col = hoff + nh * 32 + nt * 8 + lt * 2;
            *(float2*)(y + (size_t)row0 * EMB + col)
                = make_float2(to_tf32(oc[nt][0]), to_tf32(oc[nt][1]));
            *(float2*)(y + (size_t)(row0 + 8) * EMB + col)
                = make_float2(to_tf32(oc[nt][2]), to_tf32(oc[nt][3]));
        }
    }
}

// ---------------------------------------------------------------------------
// Launch
// ---------------------------------------------------------------------------
extern "C" void kernel_launch(void* const* d_in, const int* in_sizes, int n_in,
                              void* d_out, int out_size)
{
    const float* x      = (const float*)d_in[0];  // [128,256,384]
    const float* W_attn = (const float*)d_in[1];  // [384,1152]
    const float* b_attn = (const float*)d_in[2];  // [1152]
    const float* W_proj = (const float*)d_in[3];  // [384,384]
    const float* b_proj = (const float*)d_in[4];  // [384]
    float* out = (float*)d_out;                   // [128,256,384]

    float *qkv_ptr = nullptr, *y_ptr = nullptr;
    float *xr_ptr = nullptr, *war_ptr = nullptr, *wpr_ptr = nullptr;
    cudaGetSymbolAddress((void**)&qkv_ptr, g_qkv);
    cudaGetSymbolAddress((void**)&y_ptr, g_y);
    cudaGetSymbolAddress((void**)&xr_ptr, g_xr);
    cudaGetSymbolAddress((void**)&war_ptr, g_war);
    cudaGetSymbolAddress((void**)&wpr_ptr, g_wpr);

    // 0) pre-round GEMM inputs to tf32 (cheap bandwidth passes)
    {
        const int nx = M_ROWS * EMB / 4;
        round_tf32_kernel<<<2048, 256>>>(x, xr_ptr, nx);
        const int na = EMB * QKV_N / 4;
        round_tf32_kernel<<<432, 256>>>(W_attn, war_ptr, na);
        const int np = EMB * EMB / 4;
        round_tf32_kernel<<<144, 256>>>(W_proj, wpr_ptr, np);
    }

    const int gemm_smem = GEMM_SMEM_F * (int)sizeof(float);   // 75776 B
    cudaFuncSetAttribute(gemm_tf32_kernel, cudaFuncAttributeMaxDynamicSharedMemorySize, gemm_smem);

    // 1) qkv = xr @ W_attn_r + b_attn
    {
        dim3 grid(QKV_N / GBN, M_ROWS / GBM);
        gemm_tf32_kernel<<<grid, 256, gemm_smem>>>(xr_ptr, war_ptr, b_attn, qkv_ptr, QKV_N);
    }

    // 2) banded attention (tensor cores) -> g_y (tf32-rounded)
    {
        const int smem_bytes = SM_TOTF * (int)sizeof(float);   // 84 KB
        cudaFuncSetAttribute(attn_kernel, cudaFuncAttributeMaxDynamicSharedMemorySize, smem_bytes);
        dim3 grid(T_SEQ / QT, NH, B_SZ);
        attn_kernel<<<grid, 256, smem_bytes>>>(qkv_ptr, y_ptr);
    }

    // 3) out = y @ W_proj_r + b_proj
    {
        dim3 grid(EMB / GBN, M_ROWS / GBM);
        gemm_tf32_kernel<<<grid, 256, gemm_smem>>>(y_ptr, wpr_ptr, b_proj, out, EMB);
    }
}

// round 14
// speedup vs baseline: 1.6867x; 1.0590x over previous
#include <cuda_runtime.h>
#include <cuda_bf16.h>
#include <math.h>
#include <stdint.h>

// Problem constants
#define B_SZ   128
#define T_SEQ  256
#define EMB    384
#define NH     6
#define HD     64
#define WIN    64
#define M_ROWS (B_SZ * T_SEQ)        // 32768
#define QKV_N  (3 * EMB)             // 1152

// Scratch (no cudaMalloc allowed) — device globals.
__device__ float g_qkv[(size_t)M_ROWS * QKV_N];  // [M, 1152]
__device__ float g_y[(size_t)M_ROWS * EMB];      // [M, 384] tf32, k-permuted
__device__ float g_xr[(size_t)M_ROWS * EMB];     // tf32, k-permuted x
__device__ float g_war[(size_t)EMB * QKV_N];     // tf32 W_attn
__device__ float g_wpr[(size_t)EMB * EMB];       // tf32 W_proj

// ---------------------------------------------------------------------------
// tf32 + permutation helpers
// ---------------------------------------------------------------------------
__device__ __forceinline__ float to_tf32(float x) {
    uint32_t u;
    asm("cvt.rna.tf32.f32 %0, %1;" : "=r"(u) : "f"(x));
    return __uint_as_float(u);
}
// k-permutation within a 16-block: pairs (k, k+4) -> adjacent positions.
__device__ __forceinline__ int permk(int k) {
    return (k & 8) + 2 * (k & 3) + ((k >> 2) & 1);
}
__device__ __forceinline__ int invp(int p) {
    return (p & 8) | ((p >> 1) & 3) | ((p & 1) << 2);
}

__device__ __forceinline__ void mma_tf32(float c[4],
    uint32_t a0, uint32_t a1, uint32_t a2, uint32_t a3,
    uint32_t b0, uint32_t b1)
{
    asm volatile(
        "mma.sync.aligned.m16n8k8.row.col.f32.tf32.tf32.f32 "
        "{%0,%1,%2,%3}, {%4,%5,%6,%7}, {%8,%9}, {%0,%1,%2,%3};"
        : "+f"(c[0]), "+f"(c[1]), "+f"(c[2]), "+f"(c[3])
        : "r"(a0), "r"(a1), "r"(a2), "r"(a3), "r"(b0), "r"(b1));
}

__device__ __forceinline__ void cp_async16(uint32_t saddr, const float* g) {
    asm volatile("cp.async.cg.shared.global [%0], [%1], 16;" :: "r"(saddr), "l"(g));
}
#define CP_COMMIT() asm volatile("cp.async.commit_group;" ::: "memory")
#define CP_WAIT(n)  asm volatile("cp.async.wait_group %0;" :: "n"(n) : "memory")

// ---------------------------------------------------------------------------
// Pre-round kernels
// ---------------------------------------------------------------------------
__global__ void round_tf32_kernel(const float* __restrict__ in,
                                  float* __restrict__ out, int n4)
{
    for (int i = blockIdx.x * blockDim.x + threadIdx.x; i < n4;
         i += gridDim.x * blockDim.x) {
        float4 v = ((const float4*)in)[i];
        v.x = to_tf32(v.x); v.y = to_tf32(v.y);
        v.z = to_tf32(v.z); v.w = to_tf32(v.w);
        ((float4*)out)[i] = v;
    }
}

// out stored k-permuted within each 16-float block; coalesced float4 writes.
__global__ void round_tf32_perm_kernel(const float* __restrict__ in,
                                       float* __restrict__ out, int n4)
{
    for (int i = blockIdx.x * blockDim.x + threadIdx.x; i < n4;
         i += gridDim.x * blockDim.x) {
        const int blk = (i >> 2) << 4;
        const int p0  = (i & 3) * 4;
        float4 v;
        v.x = to_tf32(in[blk + invp(p0 + 0)]);
        v.y = to_tf32(in[blk + invp(p0 + 1)]);
        v.z = to_tf32(in[blk + invp(p0 + 2)]);
        v.w = to_tf32(in[blk + invp(p0 + 3)]);
        ((float4*)out)[i] = v;
    }
}

// ---------------------------------------------------------------------------
// tf32 tensor-core GEMM, 5-stage cp.async pipeline.
// A is stored k-PERMUTED (pairs (k,k+4) adjacent) -> A fragments via LDS.64.
// C[M,N] = A[M,384] @ B[384,N] + bias[N]
// BM=128, BN=128, BK=16, 256 threads (8 warps 2x4), warp tile 64x32.
// A smem [m][k'] stride 24 (LDS.64 conflict-free); B smem [k][n] stride 136.
// ---------------------------------------------------------------------------
#define GBM 128
#define GBN 128
#define GBK 16
#define AS_ST 24
#define BS_ST 136
#define NKT (EMB / GBK)          // 24
#define STAGES 5
#define AS_STAGE (GBM * AS_ST)   // 3072 floats
#define BS_STAGE (GBK * BS_ST)   // 2176 floats
#define GEMM_SMEM_F (STAGES * (AS_STAGE + BS_STAGE))   // 26240 floats = 104960 B

__global__ __launch_bounds__(256, 2) void gemm_tf32_kernel(
    const float* __restrict__ A, const float* __restrict__ Bm,
    const float* __restrict__ bias, float* __restrict__ C, int N)
{
    extern __shared__ float smem[];
    float* As = smem;                          // [STAGES][GBM][AS_ST]
    float* Bs = smem + STAGES * AS_STAGE;      // [STAGES][GBK][BS_ST]
    const uint32_t smem_base = (uint32_t)__cvta_generic_to_shared(smem);
    const uint32_t bs_base   = smem_base + STAGES * AS_STAGE * 4u;

    const int tid  = threadIdx.x;
    const int lane = tid & 31;
    const int wid  = tid >> 5;
    const int warp_m = wid >> 2;   // 0..1
    const int warp_n = wid & 3;    // 0..3
    const int m0 = blockIdx.y * GBM;
    const int n0 = blockIdx.x * GBN;

    const int ar = tid >> 2;          // 0..63 (rows ar, ar+64)
    const int ak = (tid & 3) * 4;     // 0,4,8,12 (stored-order chunk)
    const int bk = tid >> 4;          // 0..15
    const int bn = (tid & 15) * 4;    // cols bn, bn+64

    const float* Ag = A + (size_t)m0 * EMB;
    const float* Bg = Bm + n0;

    const uint32_t a_off0 = (uint32_t)((ar * AS_ST + ak) * 4);
    const uint32_t a_off1 = (uint32_t)(((ar + 64) * AS_ST + ak) * 4);
    const uint32_t b_off0 = (uint32_t)((bk * BS_ST + bn) * 4);
    const uint32_t b_off1 = (uint32_t)((bk * BS_ST + bn + 64) * 4);

    auto issue_stage = [&](int kt, int s) {
        const int k0 = kt * GBK;
        const uint32_t as_s = smem_base + (uint32_t)(s * AS_STAGE * 4);
        const uint32_t bs_s = bs_base   + (uint32_t)(s * BS_STAGE * 4);
        cp_async16(as_s + a_off0, Ag + (size_t)ar * EMB + k0 + ak);
        cp_async16(as_s + a_off1, Ag + (size_t)(ar + 64) * EMB + k0 + ak);
        cp_async16(bs_s + b_off0, Bg + (size_t)(k0 + bk) * N + bn);
        cp_async16(bs_s + b_off1, Bg + (size_t)(k0 + bk) * N + bn + 64);
        CP_COMMIT();
    };

    float c[4][4][4];
    #pragma unroll
    for (int mt = 0; mt < 4; mt++)
        #pragma unroll
        for (int nt = 0; nt < 4; nt++)
            #pragma unroll
            for (int i = 0; i < 4; i++) c[mt][nt][i] = 0.f;

    #pragma unroll
    for (int s = 0; s < STAGES - 1; s++) issue_stage(s, s);

    const int lg = lane >> 2;
    const int lt = lane & 3;

    #pragma unroll 1
    for (int kt = 0; kt < NKT; kt++) {
        CP_WAIT(STAGES - 2);
        __syncthreads();

        // Keep group count exact in the tail with empty commit groups so the
        // constant wait above always proves group kt has landed.
        const int nk = kt + STAGES - 1;
        if (nk < NKT) issue_stage(nk, nk % STAGES);
        else          CP_COMMIT();

        const int s = kt % STAGES;
        const float* as = As + s * AS_STAGE;
        const float* bs = Bs + s * BS_STAGE;

        uint32_t bfr[2][4][2];
        float2   afr[2][4][2];
        #pragma unroll
        for (int h = 0; h < 2; h++) {
            #pragma unroll
            for (int nt = 0; nt < 4; nt++) {
                const int nb = warp_n * 32 + nt * 8 + lg;
                bfr[h][nt][0] = __float_as_uint(bs[(h * 8 + lt) * BS_ST + nb]);
                bfr[h][nt][1] = __float_as_uint(bs[(h * 8 + 4 + lt) * BS_ST + nb]);
            }
            #pragma unroll
            for (int mt = 0; mt < 4; mt++) {
                const int mb = warp_m * 64 + mt * 16 + lg;
                afr[h][mt][0] = *(const float2*)&as[mb * AS_ST + h * 8 + 2 * lt];
                afr[h][mt][1] = *(const float2*)&as[(mb + 8) * AS_ST + h * 8 + 2 * lt];
            }
        }
        #pragma unroll
        for (int h = 0; h < 2; h++) {
            #pragma unroll
            for (int mt = 0; mt < 4; mt++) {
                const uint32_t a0 = __float_as_uint(afr[h][mt][0].x);
                const uint32_t a2 = __float_as_uint(afr[h][mt][0].y);
                const uint32_t a1 = __float_as_uint(afr[h][mt][1].x);
                const uint32_t a3 = __float_as_uint(afr[h][mt][1].y);
                #pragma unroll
                for (int nt = 0; nt < 4; nt++)
                    mma_tf32(c[mt][nt], a0, a1, a2, a3, bfr[h][nt][0], bfr[h][nt][1]);
            }
        }
    }

    // epilogue: add bias, store (canonical layout)
    #pragma unroll
    for (int mt = 0; mt < 4; mt++) {
        const int row = m0 + warp_m * 64 + mt * 16 + lg;
        #pragma unroll
        for (int nt = 0; nt < 4; nt++) {
            const int col = n0 + warp_n * 32 + nt * 8 + lt * 2;
            const float b0 = bias[col], b1 = bias[col + 1];
            float2 v0 = make_float2(c[mt][nt][0] + b0, c[mt][nt][1] + b1);
            float2 v1 = make_float2(c[mt][nt][2] + b0, c[mt][nt][3] + b1);
            *(float2*)&C[(size_t)row * N + col]       = v0;
            *(float2*)&C[(size_t)(row + 8) * N + col] = v1;
        }
    }
}

// ---------------------------------------------------------------------------
// Banded causal attention — tensor-core version with band skipping.
// Epilogue writes g_y tf32-rounded AND k-permuted (GEMM2's A operand).
// ---------------------------------------------------------------------------
#define QT 64
#define KT 128
#define QS_ST 68
#define KS_ST 68
#define VT_ST 132
#define SS_ST 136

#define SM_VT   0
#define SM_Q    (64 * VT_ST)
#define SM_K    (SM_Q + QT * QS_ST)
#define SM_S    SM_Q
#define SM_TOTF (SM_K + KT * KS_ST)   // 21504 floats = 84 KB

__global__ __launch_bounds__(256, 2) void attn_kernel(
    const float* __restrict__ qkv, float* __restrict__ y)
{
    extern __shared__ float sm[];
    float* Vt = sm + SM_VT;
    float* Qs = sm + SM_Q;
    float* Ks = sm + SM_K;
    float* Ss = sm + SM_S;

    const int q0  = blockIdx.x * QT;
    const int h   = blockIdx.y;
    const int b   = blockIdx.z;
    const int tid = threadIdx.x;
    const int hoff = h * HD;

    const float* base = qkv + (size_t)b * T_SEQ * QKV_N;

    for (int idx = tid; idx < KT * 16; idx += 256) {
        const int s = idx >> 4, f = idx & 15;
        const int j = q0 - WIN + s;
        float4 kv, vv;
        if (j >= 0 && j < T_SEQ) {
            const float* row = base + (size_t)j * QKV_N;
            kv = *(const float4*)(row + EMB     + hoff + f * 4);
            vv = *(const float4*)(row + 2 * EMB + hoff + f * 4);
        } else {
            kv = make_float4(0.f, 0.f, 0.f, 0.f);
            vv = kv;
        }
        float4 t;
        t.x = to_tf32(kv.x); t.y = to_tf32(kv.y); t.z = to_tf32(kv.z); t.w = to_tf32(kv.w);
        *(float4*)(Ks + s * KS_ST + f * 4) = t;
        Vt[(f * 4 + 0) * VT_ST + s] = to_tf32(vv.x);
        Vt[(f * 4 + 1) * VT_ST + s] = to_tf32(vv.y);
        Vt[(f * 4 + 2) * VT_ST + s] = to_tf32(vv.z);
        Vt[(f * 4 + 3) * VT_ST + s] = to_tf32(vv.w);
    }
    for (int idx = tid; idx < QT * 16; idx += 256) {
        const int qi = idx >> 4, f = idx & 15;
        const float* row = base + (size_t)(q0 + qi) * QKV_N;
        float4 q4 = *(const float4*)(row + hoff + f * 4);
        float4 t;
        t.x = to_tf32(q4.x); t.y = to_tf32(q4.y); t.z = to_tf32(q4.z); t.w = to_tf32(q4.w);
        *(float4*)(Qs + qi * QS_ST + f * 4) = t;
    }
    __syncthreads();

    const int lane = tid & 31;
    const int wid  = tid >> 5;
    const int lg = lane >> 2;
    const int lt = lane & 3;
    const int mt = wid & 3;
    const int nh = wid >> 2;
    const int mrow = mt * 16 + lg;

    // Valid slot band for this warp's 16-query tile.
    const int lo = max(mt * 16, WIN - q0);
    const int hi = mt * 16 + 15 + WIN;

    // ---- phase 1: S = Q @ K^T, skipping fully-masked n-chunks ----
    float sc[8][4];
    #pragma unroll
    for (int nt = 0; nt < 8; nt++)
        #pragma unroll
        for (int i = 0; i < 4; i++) sc[nt][i] = 0.f;

    bool ntv[8];
    #pragma unroll
    for (int nt = 0; nt < 8; nt++) {
        const int cb = nh * 64 + nt * 8;
        ntv[nt] = (cb + 7 >= lo) && (cb <= hi);
    }

    #pragma unroll
    for (int k0 = 0; k0 < HD; k0 += 8) {
        uint32_t a0 = __float_as_uint(Qs[mrow * QS_ST + k0 + lt]);
        uint32_t a1 = __float_as_uint(Qs[(mrow + 8) * QS_ST + k0 + lt]);
        uint32_t a2 = __float_as_uint(Qs[mrow * QS_ST + k0 + 4 + lt]);
        uint32_t a3 = __float_as_uint(Qs[(mrow + 8) * QS_ST + k0 + 4 + lt]);
        #pragma unroll
        for (int nt = 0; nt < 8; nt++) {
            if (!ntv[nt]) continue;
            const int nb = nh * 64 + nt * 8 + lg;
            uint32_t b0 = __float_as_uint(Ks[nb * KS_ST + k0 + lt]);
            uint32_t b1 = __float_as_uint(Ks[nb * KS_ST + k0 + 4 + lt]);
            mma_tf32(sc[nt], a0, a1, a2, a3, b0, b1);
        }
    }
    __syncthreads();

    #pragma unroll
    for (int nt = 0; nt < 8; nt++) {
        const int col = nh * 64 + nt * 8 + lt * 2;
        *(float2*)(Ss + mrow * SS_ST + col)       = make_float2(sc[nt][0], sc[nt][1]);
        *(float2*)(Ss + (mrow + 8) * SS_ST + col) = make_float2(sc[nt][2], sc[nt][3]);
    }
    __syncthreads();

    // ---- phase 2: masked softmax ----
    {
        const int qi = tid >> 2;
        const int kg = tid & 3;
        const int smin = max(qi, WIN - q0);
        const int smax = qi + WIN;
        float* srow = Ss + qi * SS_ST;

        float v[32];
        float m = -1e30f;
        #pragma unroll
        for (int si = 0; si < 32; si++) {
            const int s = si * 4 + kg;
            const bool ok = (s >= smin) && (s <= smax);
            float t = ok ? srow[s] * 0.125f : -1e30f;
            v[si] = t;
            m = fmaxf(m, t);
        }
        m = fmaxf(m, __shfl_xor_sync(0xffffffffu, m, 1));
        m = fmaxf(m, __shfl_xor_sync(0xffffffffu, m, 2));
        float ssum = 0.f;
        #pragma unroll
        for (int si = 0; si < 32; si++) {
            float e = __expf(v[si] - m);
            v[si] = e;
            ssum += e;
        }
        ssum += __shfl_xor_sync(0xffffffffu, ssum, 1);
        ssum += __shfl_xor_sync(0xffffffffu, ssum, 2);
        const float inv = 1.f / ssum;
        #pragma unroll
        for (int si = 0; si < 32; si++)
            srow[si * 4 + kg] = to_tf32(v[si] * inv);
    }
    __syncthreads();

    // ---- phase 3: O = P @ V, skipping all-zero slot chunks ----
    float oc[4][4];
    #pragma unroll
    for (int nt = 0; nt < 4; nt++)
        #pragma unroll
        for (int i = 0; i < 4; i++) oc[nt][i] = 0.f;

    #pragma unroll
    for (int k0 = 0; k0 < KT; k0 += 8) {
        if (k0 + 7 < lo || k0 > hi) continue;
        uint32_t a0 = __float_as_uint(Ss[mrow * SS_ST + k0 + lt]);
        uint32_t a1 = __float_as_uint(Ss[(mrow + 8) * SS_ST + k0 + lt]);
        uint32_t a2 = __float_as_uint(Ss[mrow * SS_ST + k0 + 4 + lt]);
        uint32_t a3 = __float_as_uint(Ss[(mrow + 8) * SS_ST + k0 + 4 + lt]);
        #pragma unroll
        for (int nt = 0; nt < 4; nt++) {
            const int nb = nh * 32 + nt * 8 + lg;
            uint32_t b0 = __float_as_uint(Vt[nb * VT_ST + k0 + lt]);
            uint32_t b1 = __float_as_uint(Vt[nb * VT_ST + k0 + 4 + lt]);
            mma_tf32(oc[nt], a0, a1, a2, a3, b0, b1);
        }
    }

    // ---- epilogue: write y tf32-rounded, k-permuted (GEMM2 A layout) ----
    {
        const int row0 = b * T_SEQ + q0 + mrow;
        #pragma unroll
        for (int nt = 0; nt < 4; nt++) {
            const int c = hoff + nh * 32 + nt * 8 + lt * 2;
            const int blk = c & ~15;
            const int o0 = permk(c & 15);
            const int o1 = permk((c & 15) + 1);
            y[(size_t)row0 * EMB + blk + o0]       = to_tf32(oc[nt][0]);
            y[(size_t)row0 * EMB + blk + o1]       = to_tf32(oc[nt][1]);
            y[(size_t)(row0 + 8) * EMB + blk + o0] = to_tf32(oc[nt][2]);
            y[(size_t)(row0 + 8) * EMB + blk + o1] = to_tf32(oc[nt][3]);
        }
    }
}

// ---------------------------------------------------------------------------
// Launch
// ---------------------------------------------------------------------------
extern "C" void kernel_launch(void* const* d_in, const int* in_sizes, int n_in,
                              void* d_out, int out_size)
{
    const float* x      = (const float*)d_in[0];  // [128,256,384]
    const float* W_attn = (const float*)d_in[1];  // [384,1152]
    const float* b_attn = (const float*)d_in[2];  // [1152]
    const float* W_proj = (const float*)d_in[3];  // [384,384]
    const float* b_proj = (const float*)d_in[4];  // [384]
    float* out = (float*)d_out;                   // [128,256,384]

    float *qkv_ptr = nullptr, *y_ptr = nullptr;
    float *xr_ptr = nullptr, *war_ptr = nullptr, *wpr_ptr = nullptr;
    cudaGetSymbolAddress((void**)&qkv_ptr, g_qkv);
    cudaGetSymbolAddress((void**)&y_ptr, g_y);
    cudaGetSymbolAddress((void**)&xr_ptr, g_xr);
    cudaGetSymbolAddress((void**)&war_ptr, g_war);
    cudaGetSymbolAddress((void**)&wpr_ptr, g_wpr);

    // 0) pre-round GEMM inputs (A operand permuted; B operands plain)
    {
        const int nx = M_ROWS * EMB / 4;
        round_tf32_perm_kernel<<<2048, 256>>>(x, xr_ptr, nx);
        const int na = EMB * QKV_N / 4;
        round_tf32_kernel<<<432, 256>>>(W_attn, war_ptr, na);
        const int np = EMB * EMB / 4;
        round_tf32_kernel<<<144, 256>>>(W_proj, wpr_ptr, np);
    }

    const int gemm_smem = GEMM_SMEM_F * (int)sizeof(float);   // 104960 B
    cudaFuncSetAttribute(gemm_tf32_kernel, cudaFuncAttributeMaxDynamicSharedMemorySize, gemm_smem);

    // 1) qkv = xr @ W_attn_r + b_attn
    {
        dim3 grid(QKV_N / GBN, M_ROWS / GBM);
        gemm_tf32_kernel<<<grid, 256, gemm_smem>>>(xr_ptr, war_ptr, b_attn, qkv_ptr, QKV_N);
    }

    // 2) banded attention (tensor cores) -> g_y (tf32, permuted)
    {
        const int smem_bytes = SM_TOTF * (int)sizeof(float);   // 84 KB
        cudaFuncSetAttribute(attn_kernel, cudaFuncAttributeMaxDynamicSharedMemorySize, smem_bytes);
        dim3 grid(T_SEQ / QT, NH, B_SZ);
        attn_kernel<<<grid, 256, smem_bytes>>>(qkv_ptr, y_ptr);
    }

    // 3) out = y @ W_proj_r + b_proj
    {
        dim3 grid(EMB / GBN, M_ROWS / GBM);
        gemm_tf32_kernel<<<grid, 256, gemm_smem>>>(y_ptr, wpr_ptr, b_proj, out, EMB);
    }
}

// round 15
// speedup vs baseline: 1.7137x; 1.0160x over previous
#include <cuda_runtime.h>
#include <cuda_bf16.h>
#include <math.h>
#include <stdint.h>

// Problem constants
#define B_SZ   128
#define T_SEQ  256
#define EMB    384
#define NH     6
#define HD     64
#define WIN    64
#define M_ROWS (B_SZ * T_SEQ)        // 32768
#define QKV_N  (3 * EMB)             // 1152

// Scratch (no cudaMalloc allowed) — device globals.
__device__ float g_qkv[(size_t)M_ROWS * QKV_N];  // [M, 1152]
__device__ float g_y[(size_t)M_ROWS * EMB];      // [M, 384] tf32, A-permuted
__device__ float g_xr[(size_t)M_ROWS * EMB];     // tf32, A-permuted x
__device__ float g_war[(size_t)EMB * QKV_N];     // tf32 W_attn, pair-packed
__device__ float g_wpr[(size_t)EMB * EMB];       // tf32 W_proj, pair-packed

// ---------------------------------------------------------------------------
// tf32 + permutation helpers
// ---------------------------------------------------------------------------
__device__ __forceinline__ float to_tf32(float x) {
    uint32_t u;
    asm("cvt.rna.tf32.f32 %0, %1;" : "=r"(u) : "f"(x));
    return __uint_as_float(u);
}
// A-side k-permutation within a 16-block: pairs (k, k+4) adjacent.
__device__ __forceinline__ int permk(int k) {
    return (k & 8) + 2 * (k & 3) + ((k >> 2) & 1);
}
__device__ __forceinline__ int invp(int p) {
    return (p & 8) | ((p >> 1) & 3) | ((p & 1) << 2);
}

__device__ __forceinline__ void mma_tf32(float c[4],
    uint32_t a0, uint32_t a1, uint32_t a2, uint32_t a3,
    uint32_t b0, uint32_t b1)
{
    asm volatile(
        "mma.sync.aligned.m16n8k8.row.col.f32.tf32.tf32.f32 "
        "{%0,%1,%2,%3}, {%4,%5,%6,%7}, {%8,%9}, {%0,%1,%2,%3};"
        : "+f"(c[0]), "+f"(c[1]), "+f"(c[2]), "+f"(c[3])
        : "r"(a0), "r"(a1), "r"(a2), "r"(a3), "r"(b0), "r"(b1));
}

__device__ __forceinline__ void cp_async16(uint32_t saddr, const float* g) {
    asm volatile("cp.async.cg.shared.global [%0], [%1], 16;" :: "r"(saddr), "l"(g));
}
#define CP_COMMIT() asm volatile("cp.async.commit_group;" ::: "memory")
#define CP_WAIT(n)  asm volatile("cp.async.wait_group %0;" :: "n"(n) : "memory")

// ---------------------------------------------------------------------------
// Pre-transform kernels
// ---------------------------------------------------------------------------
// A operand: tf32 + k-permuted within each 16-float block.
__global__ void round_tf32_perm_kernel(const float* __restrict__ in,
                                       float* __restrict__ out, int n4)
{
    for (int i = blockIdx.x * blockDim.x + threadIdx.x; i < n4;
         i += gridDim.x * blockDim.x) {
        const int blk = (i >> 2) << 4;
        const int p0  = (i & 3) * 4;
        float4 v;
        v.x = to_tf32(in[blk + invp(p0 + 0)]);
        v.y = to_tf32(in[blk + invp(p0 + 1)]);
        v.z = to_tf32(in[blk + invp(p0 + 2)]);
        v.w = to_tf32(in[blk + invp(p0 + 3)]);
        ((float4*)out)[i] = v;
    }
}

// B operand (weights): pack W[384][N] into Wp[[kb][r][n][p]]:
//   k = kb*16 + (r>>2)*8 + (r&3) + 4*p,  addr = (kb*8+r)*(2N) + 2n + p.
// Each output float4 covers (n0,p0)(n0,p1)(n0+1,p0)(n0+1,p1).
__global__ void pack_w_kernel(const float* __restrict__ in,
                              float* __restrict__ out, int N, int n4)
{
    for (int i = blockIdx.x * blockDim.x + threadIdx.x; i < n4;
         i += gridDim.x * blockDim.x) {
        const int pos = i * 4;
        const int row = pos / (2 * N);      // kb*8 + r
        const int rem = pos % (2 * N);
        const int n0  = rem >> 1;
        const int kb  = row >> 3, r = row & 7;
        const int k0  = kb * 16 + (r >> 2) * 8 + (r & 3);
        const int k1  = k0 + 4;
        float4 v;
        v.x = to_tf32(in[(size_t)k0 * N + n0]);
        v.y = to_tf32(in[(size_t)k1 * N + n0]);
        v.z = to_tf32(in[(size_t)k0 * N + n0 + 1]);
        v.w = to_tf32(in[(size_t)k1 * N + n0 + 1]);
        ((float4*)out)[i] = v;
    }
}

// ---------------------------------------------------------------------------
// tf32 tensor-core GEMM, 5-stage cp.async pipeline, all-LDS.64 fragments.
// C[M,N] = A[M,384] @ B[384,N] + bias[N]
// A stored k-permuted; B stored pair-packed (see pack_w_kernel).
// BM=128, BN=128, BK=16, 256 threads (8 warps 2x4), warp tile 64x32.
// A smem [m][k'] stride 24; B smem [8 rows][128 n][2] row stride 264.
// ---------------------------------------------------------------------------
#define GBM 128
#define GBN 128
#define GBK 16
#define AS_ST 24
#define BS_ST 264
#define NKT (EMB / GBK)          // 24
#define STAGES 5
#define AS_STAGE (GBM * AS_ST)   // 3072 floats
#define BS_STAGE (8 * BS_ST)     // 2112 floats
#define GEMM_SMEM_F (STAGES * (AS_STAGE + BS_STAGE))   // 25920 floats = 103680 B

__global__ __launch_bounds__(256, 2) void gemm_tf32_kernel(
    const float* __restrict__ A, const float* __restrict__ Bm,
    const float* __restrict__ bias, float* __restrict__ C, int N)
{
    extern __shared__ float smem[];
    float* As = smem;                          // [STAGES][GBM][AS_ST]
    float* Bs = smem + STAGES * AS_STAGE;      // [STAGES][8][BS_ST]
    const uint32_t smem_base = (uint32_t)__cvta_generic_to_shared(smem);
    const uint32_t bs_base   = smem_base + STAGES * AS_STAGE * 4u;

    const int tid  = threadIdx.x;
    const int lane = tid & 31;
    const int wid  = tid >> 5;
    const int warp_m = wid >> 2;   // 0..1
    const int warp_n = wid & 3;    // 0..3
    const int m0 = blockIdx.y * GBM;
    const int n0 = blockIdx.x * GBN;

    // A loader: rows ar, ar+64; 16B chunk ak
    const int ar = tid >> 2;
    const int ak = (tid & 3) * 4;
    // B loader: row br (0..7), chunks bc, bc+32 (64 float4 per row of 256)
    const int br = tid >> 5;
    const int bc = tid & 31;

    const float* Ag = A + (size_t)m0 * EMB;
    const float* Bg = Bm + (size_t)n0 * 2;   // packed: 2 floats per n

    const uint32_t a_off0 = (uint32_t)((ar * AS_ST + ak) * 4);
    const uint32_t a_off1 = (uint32_t)(((ar + 64) * AS_ST + ak) * 4);
    const uint32_t b_off0 = (uint32_t)((br * BS_ST + bc * 4) * 4);
    const uint32_t b_off1 = (uint32_t)((br * BS_ST + bc * 4 + 128) * 4);

    auto issue_stage = [&](int kt, int s) {
        const int k0 = kt * GBK;
        const uint32_t as_s = smem_base + (uint32_t)(s * AS_STAGE * 4);
        const uint32_t bs_s = bs_base   + (uint32_t)(s * BS_STAGE * 4);
        cp_async16(as_s + a_off0, Ag + (size_t)ar * EMB + k0 + ak);
        cp_async16(as_s + a_off1, Ag + (size_t)(ar + 64) * EMB + k0 + ak);
        const float* brow = Bg + (size_t)(kt * 8 + br) * (2 * N);
        cp_async16(bs_s + b_off0, brow + bc * 4);
        cp_async16(bs_s + b_off1, brow + bc * 4 + 128);
        CP_COMMIT();
    };

    float c[4][4][4];
    #pragma unroll
    for (int mt = 0; mt < 4; mt++)
        #pragma unroll
        for (int nt = 0; nt < 4; nt++)
            #pragma unroll
            for (int i = 0; i < 4; i++) c[mt][nt][i] = 0.f;

    #pragma unroll
    for (int s = 0; s < STAGES - 1; s++) issue_stage(s, s);

    const int lg = lane >> 2;
    const int lt = lane & 3;

    #pragma unroll 1
    for (int kt = 0; kt < NKT; kt++) {
        CP_WAIT(STAGES - 2);
        __syncthreads();

        const int nk = kt + STAGES - 1;
        if (nk < NKT) issue_stage(nk, nk % STAGES);
        else          CP_COMMIT();   // keep group arithmetic exact in tail

        const int s = kt % STAGES;
        const float* as = As + s * AS_STAGE;
        const float* bs = Bs + s * BS_STAGE;

        float2 bfr[2][4];
        float2 afr[2][4][2];
        #pragma unroll
        for (int h = 0; h < 2; h++) {
            #pragma unroll
            for (int nt = 0; nt < 4; nt++) {
                const int nb2 = (warp_n * 32 + nt * 8 + lg) * 2;
                bfr[h][nt] = *(const float2*)&bs[(h * 4 + lt) * BS_ST + nb2];
            }
            #pragma unroll
            for (int mt = 0; mt < 4; mt++) {
                const int mb = warp_m * 64 + mt * 16 + lg;
                afr[h][mt][0] = *(const float2*)&as[mb * AS_ST + h * 8 + 2 * lt];
                afr[h][mt][1] = *(const float2*)&as[(mb + 8) * AS_ST + h * 8 + 2 * lt];
            }
        }
        #pragma unroll
        for (int h = 0; h < 2; h++) {
            #pragma unroll
            for (int mt = 0; mt < 4; mt++) {
                const uint32_t a0 = __float_as_uint(afr[h][mt][0].x);
                const uint32_t a2 = __float_as_uint(afr[h][mt][0].y);
                const uint32_t a1 = __float_as_uint(afr[h][mt][1].x);
                const uint32_t a3 = __float_as_uint(afr[h][mt][1].y);
                #pragma unroll
                for (int nt = 0; nt < 4; nt++)
                    mma_tf32(c[mt][nt], a0, a1, a2, a3,
                             __float_as_uint(bfr[h][nt].x),
                             __float_as_uint(bfr[h][nt].y));
            }
        }
    }

    // epilogue: add bias, store (canonical layout)
    #pragma unroll
    for (int mt = 0; mt < 4; mt++) {
        const int row = m0 + warp_m * 64 + mt * 16 + lg;
        #pragma unroll
        for (int nt = 0; nt < 4; nt++) {
            const int col = n0 + warp_n * 32 + nt * 8 + lt * 2;
            const float b0 = bias[col], b1 = bias[col + 1];
            float2 v0 = make_float2(c[mt][nt][0] + b0, c[mt][nt][1] + b1);
            float2 v1 = make_float2(c[mt][nt][2] + b0, c[mt][nt][3] + b1);
            *(float2*)&C[(size_t)row * N + col]       = v0;
            *(float2*)&C[(size_t)(row + 8) * N + col] = v1;
        }
    }
}

// ---------------------------------------------------------------------------
// Banded causal attention — tensor cores, band skipping.
// Q/K stored with d-dimension pair-permuted (stride 72) -> LDS.64 fragments.
// V stored row-major [s][d] stride 72 -> direct col-major B reads, no transpose.
// Epilogue writes g_y tf32-rounded AND A-permuted (GEMM2's A operand).
// ---------------------------------------------------------------------------
#define QT 64
#define KT 128
#define QK_ST 72    // 72 % 32 == 8 -> paired frag loads conflict-free
#define VS_ST 72
#define SS_ST 136

#define SM_V    0
#define SM_Q    (KT * VS_ST)             // 9216
#define SM_K    (SM_Q + QT * QK_ST)      // 13824
#define SM_S    SM_Q                     // S aliases Q+K after phase 1
#define SM_TOTF (SM_K + KT * QK_ST)      // 23040 floats = 92160 B

__global__ __launch_bounds__(256, 2) void attn_kernel(
    const float* __restrict__ qkv, float* __restrict__ y)
{
    extern __shared__ float sm[];
    float* Vs = sm + SM_V;    // [s=128][d=64], stride 72
    float* Qs = sm + SM_Q;    // [q=64][d' permuted], stride 72
    float* Ks = sm + SM_K;    // [s=128][d' permuted], stride 72
    float* Ss = sm + SM_S;    // [q=64][s=128], stride 136

    const int q0  = blockIdx.x * QT;
    const int h   = blockIdx.y;
    const int b   = blockIdx.z;
    const int tid = threadIdx.x;
    const int hoff = h * HD;

    const float* base = qkv + (size_t)b * T_SEQ * QKV_N;

    // ---- K: permuted-d rows (8-float granularity, register shuffle) ----
    for (int idx = tid; idx < KT * 8; idx += 256) {
        const int s = idx >> 3, g = idx & 7;
        const int j = q0 - WIN + s;
        float4 c0, c1;
        if (j >= 0 && j < T_SEQ) {
            const float* row = base + (size_t)j * QKV_N + EMB + hoff + g * 8;
            c0 = *(const float4*)(row);
            c1 = *(const float4*)(row + 4);
        } else {
            c0 = make_float4(0.f, 0.f, 0.f, 0.f);
            c1 = c0;
        }
        float4 o0 = make_float4(to_tf32(c0.x), to_tf32(c1.x), to_tf32(c0.y), to_tf32(c1.y));
        float4 o1 = make_float4(to_tf32(c0.z), to_tf32(c1.z), to_tf32(c0.w), to_tf32(c1.w));
        *(float4*)(Ks + s * QK_ST + g * 8)     = o0;
        *(float4*)(Ks + s * QK_ST + g * 8 + 4) = o1;
    }
    // ---- Q: permuted-d rows ----
    for (int idx = tid; idx < QT * 8; idx += 256) {
        const int qi = idx >> 3, g = idx & 7;
        const float* row = base + (size_t)(q0 + qi) * QKV_N + hoff + g * 8;
        float4 c0 = *(const float4*)(row);
        float4 c1 = *(const float4*)(row + 4);
        float4 o0 = make_float4(to_tf32(c0.x), to_tf32(c1.x), to_tf32(c0.y), to_tf32(c1.y));
        float4 o1 = make_float4(to_tf32(c0.z), to_tf32(c1.z), to_tf32(c0.w), to_tf32(c1.w));
        *(float4*)(Qs + qi * QK_ST + g * 8)     = o0;
        *(float4*)(Qs + qi * QK_ST + g * 8 + 4) = o1;
    }
    // ---- V: plain row-major ----
    for (int idx = tid; idx < KT * 16; idx += 256) {
        const int s = idx >> 4, f = idx & 15;
        const int j = q0 - WIN + s;
        float4 vv;
        if (j >= 0 && j < T_SEQ) {
            vv = *(const float4*)(base + (size_t)j * QKV_N + 2 * EMB + hoff + f * 4);
        } else {
            vv = make_float4(0.f, 0.f, 0.f, 0.f);
        }
        float4 t;
        t.x = to_tf32(vv.x); t.y = to_tf32(vv.y); t.z = to_tf32(vv.z); t.w = to_tf32(vv.w);
        *(float4*)(Vs + s * VS_ST + f * 4) = t;
    }
    __syncthreads();

    const int lane = tid & 31;
    const int wid  = tid >> 5;
    const int lg = lane >> 2;
    const int lt = lane & 3;
    const int mt = wid & 3;
    const int nh = wid >> 2;
    const int mrow = mt * 16 + lg;

    // Valid slot band for this warp's 16-query tile.
    const int lo = max(mt * 16, WIN - q0);
    const int hi = mt * 16 + 15 + WIN;

    // ---- phase 1: S = Q @ K^T (paired LDS.64 fragments, band-skipped) ----
    float sc[8][4];
    #pragma unroll
    for (int nt = 0; nt < 8; nt++)
        #pragma unroll
        for (int i = 0; i < 4; i++) sc[nt][i] = 0.f;

    bool ntv[8];
    #pragma unroll
    for (int nt = 0; nt < 8; nt++) {
        const int cb = nh * 64 + nt * 8;
        ntv[nt] = (cb + 7 >= lo) && (cb <= hi);
    }

    #pragma unroll
    for (int k0 = 0; k0 < HD; k0 += 8) {
        float2 aq0 = *(const float2*)&Qs[mrow * QK_ST + k0 + 2 * lt];       // (a0,a2)
        float2 aq1 = *(const float2*)&Qs[(mrow + 8) * QK_ST + k0 + 2 * lt]; // (a1,a3)
        const uint32_t a0 = __float_as_uint(aq0.x);
        const uint32_t a2 = __float_as_uint(aq0.y);
        const uint32_t a1 = __float_as_uint(aq1.x);
        const uint32_t a3 = __float_as_uint(aq1.y);
        #pragma unroll
        for (int nt = 0; nt < 8; nt++) {
            if (!ntv[nt]) continue;
            const int nb = nh * 64 + nt * 8 + lg;
            float2 bk = *(const float2*)&Ks[nb * QK_ST + k0 + 2 * lt];      // (b0,b1)
            mma_tf32(sc[nt], a0, a1, a2, a3,
                     __float_as_uint(bk.x), __float_as_uint(bk.y));
        }
    }
    __syncthreads();   // done reading Qs/Ks; Ss may overwrite

    #pragma unroll
    for (int nt = 0; nt < 8; nt++) {
        const int col = nh * 64 + nt * 8 + lt * 2;
        *(float2*)(Ss + mrow * SS_ST + col)       = make_float2(sc[nt][0], sc[nt][1]);
        *(float2*)(Ss + (mrow + 8) * SS_ST + col) = make_float2(sc[nt][2], sc[nt][3]);
    }
    __syncthreads();

    // ---- phase 2: masked softmax ----
    {
        const int qi = tid >> 2;
        const int kg = tid & 3;
        const int smin = max(qi, WIN - q0);
        const int smax = qi + WIN;
        float* srow = Ss + qi * SS_ST;

        float v[32];
        float m = -1e30f;
        #pragma unroll
        for (int si = 0; si < 32; si++) {
            const int s = si * 4 + kg;
            const bool ok = (s >= smin) && (s <= smax);
            float t = ok ? srow[s] * 0.125f : -1e30f;
            v[si] = t;
            m = fmaxf(m, t);
        }
        m = fmaxf(m, __shfl_xor_sync(0xffffffffu, m, 1));
        m = fmaxf(m, __shfl_xor_sync(0xffffffffu, m, 2));
        float ssum = 0.f;
        #pragma unroll
        for (int si = 0; si < 32; si++) {
            float e = __expf(v[si] - m);
            v[si] = e;
            ssum += e;
        }
        ssum += __shfl_xor_sync(0xffffffffu, ssum, 1);
        ssum += __shfl_xor_sync(0xffffffffu, ssum, 2);
        const float inv = 1.f / ssum;
        #pragma unroll
        for (int si = 0; si < 32; si++)
            srow[si * 4 + kg] = to_tf32(v[si] * inv);
    }
    __syncthreads();

    // ---- phase 3: O = P @ V (V row-major read as col-major B) ----
    float oc[4][4];
    #pragma unroll
    for (int nt = 0; nt < 4; nt++)
        #pragma unroll
        for (int i = 0; i < 4; i++) oc[nt][i] = 0.f;

    #pragma unroll
    for (int k0 = 0; k0 < KT; k0 += 8) {
        if (k0 + 7 < lo || k0 > hi) continue;
        uint32_t a0 = __float_as_uint(Ss[mrow * SS_ST + k0 + lt]);
        uint32_t a1 = __float_as_uint(Ss[(mrow + 8) * SS_ST + k0 + lt]);
        uint32_t a2 = __float_as_uint(Ss[mrow * SS_ST + k0 + 4 + lt]);
        uint32_t a3 = __float_as_uint(Ss[(mrow + 8) * SS_ST + k0 + 4 + lt]);
        #pragma unroll
        for (int nt = 0; nt < 4; nt++) {
            const int nb = nh * 32 + nt * 8 + lg;   // output dim d
            uint32_t b0 = __float_as_uint(Vs[(k0 + lt) * VS_ST + nb]);
            uint32_t b1 = __float_as_uint(Vs[(k0 + 4 + lt) * VS_ST + nb]);
            mma_tf32(oc[nt], a0, a1, a2, a3, b0, b1);
        }
    }

    // ---- epilogue: write y tf32-rounded, A-permuted (GEMM2 A layout) ----
    {
        const int row0 = b * T_SEQ + q0 + mrow;
        #pragma unroll
        for (int nt = 0; nt < 4; nt++) {
            const int c = hoff + nh * 32 + nt * 8 + lt * 2;
            const int blk = c & ~15;
            const int o0 = permk(c & 15);
            const int o1 = permk((c & 15) + 1);
            y[(size_t)row0 * EMB + blk + o0]       = to_tf32(oc[nt][0]);
            y[(size_t)row0 * EMB + blk + o1]       = to_tf32(oc[nt][1]);
            y[(size_t)(row0 + 8) * EMB + blk + o0] = to_tf32(oc[nt][2]);
            y[(size_t)(row0 + 8) * EMB + blk + o1] = to_tf32(oc[nt][3]);
        }
    }
}

// ---------------------------------------------------------------------------
// Launch
// ---------------------------------------------------------------------------
extern "C" void kernel_launch(void* const* d_in, const int* in_sizes, int n_in,
                              void* d_out, int out_size)
{
    const float* x      = (const float*)d_in[0];  // [128,256,384]
    const float* W_attn = (const float*)d_in[1];  // [384,1152]
    const float* b_attn = (const float*)d_in[2];  // [1152]
    const float* W_proj = (const float*)d_in[3];  // [384,384]
    const float* b_proj = (const float*)d_in[4];  // [384]
    float* out = (float*)d_out;                   // [128,256,384]

    float *qkv_ptr = nullptr, *y_ptr = nullptr;
    float *xr_ptr = nullptr, *war_ptr = nullptr, *wpr_ptr = nullptr;
    cudaGetSymbolAddress((void**)&qkv_ptr, g_qkv);
    cudaGetSymbolAddress((void**)&y_ptr, g_y);
    cudaGetSymbolAddress((void**)&xr_ptr, g_xr);
    cudaGetSymbolAddress((void**)&war_ptr, g_war);
    cudaGetSymbolAddress((void**)&wpr_ptr, g_wpr);

    // 0) pre-transform GEMM inputs (A permuted; B pair-packed)
    {
        const int nx = M_ROWS * EMB / 4;
        round_tf32_perm_kernel<<<2048, 256>>>(x, xr_ptr, nx);
        const int na = EMB * QKV_N / 4;
        pack_w_kernel<<<432, 256>>>(W_attn, war_ptr, QKV_N, na);
        const int np = EMB * EMB / 4;
        pack_w_kernel<<<144, 256>>>(W_proj, wpr_ptr, EMB, np);
    }

    const int gemm_smem = GEMM_SMEM_F * (int)sizeof(float);   // 103680 B
    cudaFuncSetAttribute(gemm_tf32_kernel, cudaFuncAttributeMaxDynamicSharedMemorySize, gemm_smem);

    // 1) qkv = xr @ W_attn_packed + b_attn
    {
        dim3 grid(QKV_N / GBN, M_ROWS / GBM);
        gemm_tf32_kernel<<<grid, 256, gemm_smem>>>(xr_ptr, war_ptr, b_attn, qkv_ptr, QKV_N);
    }

    // 2) banded attention (tensor cores) -> g_y (tf32, A-permuted)
    {
        const int smem_bytes = SM_TOTF * (int)sizeof(float);   // 92160 B
        cudaFuncSetAttribute(attn_kernel, cudaFuncAttributeMaxDynamicSharedMemorySize, smem_bytes);
        dim3 grid(T_SEQ / QT, NH, B_SZ);
        attn_kernel<<<grid, 256, smem_bytes>>>(qkv_ptr, y_ptr);
    }

    // 3) out = y @ W_proj_packed + b_proj
    {
        dim3 grid(EMB / GBN, M_ROWS / GBM);
        gemm_tf32_kernel<<<grid, 256, gemm_smem>>>(y_ptr, wpr_ptr, b_proj, out, EMB);
    }
}